// round 16
// baseline (speedup 1.0000x reference)
#include <cuda_runtime.h>
#include <cuda_bf16.h>
#include <math.h>
#include <stdint.h>

#define BB 16
#define TT 77
#define SSRC 300
#define NHID 300
#define LL 677
#define DM 512
#define NH 8
#define HD 64
#define TOKS 10832   // 16*77 + 16*300 + 16*300

// ----- arena offsets (u32/float word units) -----
#define OFF_ADA   8192L          // fp32 3*16*3072
#define OFF_NBUF  155648L        // bf16 words TOKS*256
#define OFF_QKVW  2928640L       // bf16 words 3*TOKS*256 (q,k,v token-major)
#define OFF_QAW   11247616L      // bf16 words [B*H][L][32]
#define OFF_KAW   14020608L
#define OFF_OGAT  19566592L      // bf16 words TOKS*256
#define OFF_ABUF  22339584L      // fp32 TOKS*512
#define OFF_HBUF  27885568L      // fp32 TOKS*512
#define OFF_N2    33431552L      // bf16 words TOKS*256
#define OFF_G     36204544L      // bf16 words TOKS*1024
#define OFF_WQ    47296512L      // 9 * 256*512
#define OFF_WO    48476160L      // 3 * 256*512
#define OFF_WF1   48869376L      // 3 * 256*4096
#define OFF_WF2   52015104L      // 3 * 1024*512
#define ARENA_SZ  53587968L

__device__ float d_arena[ARENA_SZ];

__device__ __forceinline__ uint32_t pack_bf(float x, float y) {
    __nv_bfloat162 h = __floats2bfloat162_rn(x, y);
    return *(uint32_t*)&h;
}
__device__ __forceinline__ float2 unpack_bf(uint32_t w) {
    __nv_bfloat162 h = *(__nv_bfloat162*)&w;
    return __bfloat1622float2(h);
}

// ---------------------------------------------------------------------------
// merged weight prepack: 4 segments in one launch (k-pair packed, row-major)
__global__ void k_wconvAll(const float* __restrict__ W0, const float* __restrict__ W1,
                           const float* __restrict__ W2, const float* __restrict__ W3) {
    int i = blockIdx.x * blockDim.x + threadIdx.x;
    const float* src;
    long dstW;
    int K2, N, base4;
    if (i < 294912)       { src = W0; dstW = OFF_WQ;  K2 = 256;  N = 512;  base4 = 0; }
    else if (i < 393216)  { src = W1; dstW = OFF_WO;  K2 = 256;  N = 512;  base4 = 294912; }
    else if (i < 1179648) { src = W2; dstW = OFF_WF1; K2 = 256;  N = 4096; base4 = 393216; }
    else if (i < 1572864) { src = W3; dstW = OFF_WF2; K2 = 1024; N = 512;  base4 = 1179648; }
    else return;
    int w = (i - base4) << 2;
    int K2N = K2 * N;
    int z = w / K2N;
    int rem = w - z * K2N;
    int k2 = rem / N;
    int n = rem - k2 * N;
    const float* s = src + (long)z * K2N * 2 + (long)(2 * k2) * N + n;
    float4 e = *(const float4*)s;
    float4 o = *(const float4*)(s + N);
    uint4 r;
    r.x = pack_bf(e.x, o.x);
    r.y = pack_bf(e.y, o.y);
    r.z = pack_bf(e.z, o.z);
    r.w = pack_bf(e.w, o.w);
    *(uint4*)&((uint32_t*)d_arena)[dstW + w] = r;
}

// ---------------------------------------------------------------------------
// ada projection SIMT GEMM, silu fused into A staging (M=16)
__global__ void k_gemm_ada(const float* __restrict__ temb,
                           const float* __restrict__ Bmat, const float* __restrict__ bias,
                           long offC, int M, int N, int K,
                           long szB, long szBias, long szC) {
    const float* Bm = Bmat + (long)blockIdx.z * szB;
    const float* bi = bias + (long)blockIdx.z * szBias;
    float*       C  = d_arena + offC + (long)blockIdx.z * szC;

    __shared__ float As[16][68];
    __shared__ float Bs[16][64];

    int tid = threadIdx.x;
    int tx = tid & 15, ty = tid >> 4;
    int arow = tid >> 2;
    int akc  = (tid & 3) << 2;
    int brow = tid >> 4;
    int bcol = (tid & 15) << 2;
    long grow  = (long)blockIdx.y * 64 + arow;
    int  gcolB = blockIdx.x * 64 + bcol;

    float acc[4][4];
#pragma unroll
    for (int i = 0; i < 4; i++)
#pragma unroll
        for (int j = 0; j < 4; j++) acc[i][j] = 0.f;

    for (int kt = 0; kt < K; kt += 16) {
        float4 a4 = make_float4(0.f, 0.f, 0.f, 0.f);
        if (grow < M) {
            a4 = *(const float4*)&temb[grow * K + kt + akc];
            a4.x = a4.x / (1.f + __expf(-a4.x));
            a4.y = a4.y / (1.f + __expf(-a4.y));
            a4.z = a4.z / (1.f + __expf(-a4.z));
            a4.w = a4.w / (1.f + __expf(-a4.w));
        }
        As[akc + 0][arow] = a4.x;
        As[akc + 1][arow] = a4.y;
        As[akc + 2][arow] = a4.z;
        As[akc + 3][arow] = a4.w;
        float4 b4 = *(const float4*)&Bm[(long)(kt + brow) * N + gcolB];
        *(float4*)&Bs[brow][bcol] = b4;
        __syncthreads();
#pragma unroll
        for (int k = 0; k < 16; k++) {
            float4 av = *(const float4*)&As[k][ty << 2];
            float4 bv = *(const float4*)&Bs[k][tx << 2];
            float a[4] = {av.x, av.y, av.z, av.w};
            float b[4] = {bv.x, bv.y, bv.z, bv.w};
#pragma unroll
            for (int i = 0; i < 4; i++)
#pragma unroll
                for (int j = 0; j < 4; j++) acc[i][j] += a[i] * b[j];
        }
        __syncthreads();
    }

    int crow0 = blockIdx.y * 64 + (ty << 2);
    int ccol0 = blockIdx.x * 64 + (tx << 2);
    float4 bi4 = *(const float4*)&bi[ccol0];
#pragma unroll
    for (int i = 0; i < 4; i++) {
        if (crow0 + i < M) {
            float4 o;
            o.x = acc[i][0] + bi4.x;
            o.y = acc[i][1] + bi4.y;
            o.z = acc[i][2] + bi4.z;
            o.w = acc[i][3] + bi4.w;
            *(float4*)&C[(long)(crow0 + i) * N + ccol0] = o;
        }
    }
}

// ---------------------------------------------------------------------------
__device__ __forceinline__ void mma_bf16(float c[4], const uint32_t a[4], const uint32_t b[2]) {
    asm volatile(
        "mma.sync.aligned.m16n8k16.row.col.f32.bf16.bf16.f32 "
        "{%0,%1,%2,%3},{%4,%5,%6,%7},{%8,%9},{%0,%1,%2,%3};"
        : "+f"(c[0]), "+f"(c[1]), "+f"(c[2]), "+f"(c[3])
        : "r"(a[0]), "r"(a[1]), "r"(a[2]), "r"(a[3]), "r"(b[0]), "r"(b[1]));
}

__device__ __forceinline__ uint32_t smem_u32(const void* p) {
    return (uint32_t)__cvta_generic_to_shared(p);
}
__device__ __forceinline__ void cp16(uint32_t dst, const void* src, int sz) {
    asm volatile("cp.async.cg.shared.global [%0], [%1], 16, %2;\n"
                 :: "r"(dst), "l"(src), "r"(sz));
}
__device__ __forceinline__ void cp_commit() { asm volatile("cp.async.commit_group;\n"); }
template <int N> __device__ __forceinline__ void cp_wait() {
    asm volatile("cp.async.wait_group %0;\n" :: "n"(N));
}

// 4-stage bf16 GEMM smem (u32 words): As[4][128][20]=10240, Bs[4][16][136]=8704
#define GT_SMEM 75776
#define AS_IDX(buf, r, k2) ((buf) * 2560 + (r) * 20 + (k2))
#define BS_IDX(buf, k2, n) (10240 + (buf) * 2176 + (k2) * 136 + (n))

// 4-stage ring, single __syncthreads per K-tile (R12-proven form).
#define BF_MAINLOOP(A, Bm, N_, Kw_, nk_)                                                   \
    for (int p = 0; p < 3; p++) {                                                          \
        if (p < (nk_)) {                                                                   \
            const uint32_t* as = (A) + arowc * (Kw_) + (p << 4) + ac0;                     \
            const uint32_t* bs = (Bm) + (long)((p << 4) + bk) * (N_) + bcol0;              \
            for (int c = 0; c < 8; c += 4) cp16(smem_u32(&dsu[AS_IDX(p, ar, ac0 + c)]), as + c, asz); \
            for (int c = 0; c < 8; c += 4) cp16(smem_u32(&dsu[BS_IDX(p, bk, bn0 + c)]), bs + c, 16);  \
        }                                                                                  \
        cp_commit();                                                                       \
    }                                                                                      \
    for (int kt = 0; kt < (nk_); kt++) {                                                   \
        cp_wait<2>();                                                                      \
        __syncthreads();                                                                   \
        if (kt + 3 < (nk_)) {                                                              \
            int nb = (kt + 3) & 3;                                                         \
            const uint32_t* as = (A) + arowc * (Kw_) + ((kt + 3) << 4) + ac0;              \
            const uint32_t* bs = (Bm) + (long)(((kt + 3) << 4) + bk) * (N_) + bcol0;       \
            for (int c = 0; c < 8; c += 4) cp16(smem_u32(&dsu[AS_IDX(nb, ar, ac0 + c)]), as + c, asz); \
            for (int c = 0; c < 8; c += 4) cp16(smem_u32(&dsu[BS_IDX(nb, bk, bn0 + c)]), bs + c, 16);  \
        }                                                                                  \
        cp_commit();                                                                       \
        int cur = kt & 3;                                                                  \
        _Pragma("unroll")                                                                  \
        for (int s8 = 0; s8 < 16; s8 += 8) {                                               \
            uint32_t af[2][4];                                                             \
            _Pragma("unroll")                                                              \
            for (int mi = 0; mi < 2; mi++) {                                               \
                int r = wm * 32 + mi * 16 + g;                                             \
                af[mi][0] = dsu[AS_IDX(cur, r, s8 + tg)];                                  \
                af[mi][1] = dsu[AS_IDX(cur, r + 8, s8 + tg)];                              \
                af[mi][2] = dsu[AS_IDX(cur, r, s8 + tg + 4)];                              \
                af[mi][3] = dsu[AS_IDX(cur, r + 8, s8 + tg + 4)];                          \
            }                                                                              \
            uint32_t bfr[8][2];                                                            \
            _Pragma("unroll")                                                              \
            for (int ni = 0; ni < 8; ni++) {                                               \
                int cn = wn * 64 + ni * 8 + g;                                             \
                bfr[ni][0] = dsu[BS_IDX(cur, s8 + tg, cn)];                                \
                bfr[ni][1] = dsu[BS_IDX(cur, s8 + 4 + tg, cn)];                            \
            }                                                                              \
            _Pragma("unroll")                                                              \
            for (int mi = 0; mi < 2; mi++)                                                 \
                _Pragma("unroll")                                                          \
                for (int ni = 0; ni < 8; ni++)                                             \
                    mma_bf16(acc[mi][ni], af[mi], bfr[ni]);                                \
        }                                                                                  \
    }

// ---------------------------------------------------------------------------
// generic bf16 GEMM -> fp32 C + bias (Wo)
struct GemmDescB {
    const float* bip;
    long szBias;
    long offA[3], offC[3];
    long bW, szBW;
    int  M[3];
    int  N, K;
};

__global__ void __launch_bounds__(256, 2)
k_gemm_bf(GemmDescB d) {
    extern __shared__ uint32_t dsu[];
    uint32_t* au = (uint32_t*)d_arena;
    int z = blockIdx.z;
    int M = d.M[z];
    int m0 = blockIdx.y * 128;
    if (m0 >= M) return;
    int N = d.N;
    int Kw = d.K >> 1;
    const uint32_t* A  = au + d.offA[z];
    const uint32_t* Bm = au + d.bW + (long)z * d.szBW;
    const float*    bi = d.bip + (long)z * d.szBias;
    float*          C  = d_arena + d.offC[z];

    int tid  = threadIdx.x;
    int lane = tid & 31, wid = tid >> 5;
    int wm = wid & 3, wn = wid >> 2;
    int g  = lane >> 2, tg = lane & 3;
    int n0 = blockIdx.x * 128;

    int ar  = tid >> 1;
    int ac0 = (tid & 1) << 3;
    int bk  = tid >> 4;
    int bn0 = (tid & 15) << 3;
    int bcol0 = n0 + bn0;

    long grow = m0 + ar;
    long arowc = (grow < M ? grow : (long)(M - 1));
    int  asz = (grow < M) ? 16 : 0;

    float acc[2][8][4];
#pragma unroll
    for (int mi = 0; mi < 2; mi++)
#pragma unroll
        for (int ni = 0; ni < 8; ni++)
#pragma unroll
            for (int r = 0; r < 4; r++) acc[mi][ni][r] = 0.f;

    int nk = d.K >> 5;
    BF_MAINLOOP(A, Bm, N, Kw, nk)

#pragma unroll
    for (int mi = 0; mi < 2; mi++) {
        int row = m0 + wm * 32 + mi * 16 + g;
#pragma unroll
        for (int ni = 0; ni < 8; ni++) {
            int col = n0 + wn * 64 + ni * 8 + tg * 2;
            float bx = bi[col], by = bi[col + 1];
            if (row < M) {
                float2 o = make_float2(acc[mi][ni][0] + bx, acc[mi][ni][1] + by);
                *(float2*)&C[(long)row * N + col] = o;
            }
            if (row + 8 < M) {
                float2 o = make_float2(acc[mi][ni][2] + bx, acc[mi][ni][3] + by);
                *(float2*)&C[(long)(row + 8) * N + col] = o;
            }
        }
    }
}

// ---------------------------------------------------------------------------
// QKV bf16 GEMM -> PACKED bf16 words (token-major [M][256]); z = s*3+j
struct QKVWDesc {
    const float* bip;
    long offA[3];
    int  M[3];
};

__global__ void __launch_bounds__(256, 2)
k_gemm_bfw(QKVWDesc d) {
    extern __shared__ uint32_t dsu[];
    uint32_t* au = (uint32_t*)d_arena;
    int z = blockIdx.z;
    int s_ = z / 3, j = z % 3;
    int M = d.M[s_];
    int m0 = blockIdx.y * 128;
    if (m0 >= M) return;
    const int N = DM, Kw = 256;
    const uint32_t* A  = au + d.offA[s_];
    const uint32_t* Bm = au + OFF_WQ + (long)z * 256 * 512;
    const float*    bi = d.bip + (long)z * DM;
    uint32_t*       Cw = au + OFF_QKVW + (long)j * TOKS * 256 +
                         (d.offA[s_] - OFF_NBUF);

    int tid  = threadIdx.x;
    int lane = tid & 31, wid = tid >> 5;
    int wm = wid & 3, wn = wid >> 2;
    int g  = lane >> 2, tg = lane & 3;
    int n0 = blockIdx.x * 128;

    int ar  = tid >> 1;
    int ac0 = (tid & 1) << 3;
    int bk  = tid >> 4;
    int bn0 = (tid & 15) << 3;
    int bcol0 = n0 + bn0;

    long grow = m0 + ar;
    long arowc = (grow < M ? grow : (long)(M - 1));
    int  asz = (grow < M) ? 16 : 0;

    float acc[2][8][4];
#pragma unroll
    for (int mi = 0; mi < 2; mi++)
#pragma unroll
        for (int ni = 0; ni < 8; ni++)
#pragma unroll
            for (int r = 0; r < 4; r++) acc[mi][ni][r] = 0.f;

    BF_MAINLOOP(A, Bm, N, Kw, 16)

#pragma unroll
    for (int mi = 0; mi < 2; mi++) {
        int row = m0 + wm * 32 + mi * 16 + g;
#pragma unroll
        for (int ni = 0; ni < 8; ni++) {
            int col = n0 + wn * 64 + ni * 8 + tg * 2;
            float bx = bi[col], by = bi[col + 1];
            if (row < M)
                Cw[(long)row * 256 + (col >> 1)] = pack_bf(acc[mi][ni][0] + bx, acc[mi][ni][1] + by);
            if (row + 8 < M)
                Cw[(long)(row + 8) * 256 + (col >> 1)] = pack_bf(acc[mi][ni][2] + bx, acc[mi][ni][3] + by);
        }
    }
}

// ---------------------------------------------------------------------------
// FF1 (bf16) fused with GeGLU -> G (bf16)
struct FF1DescB {
    const float* bip;
    long offA[3], offGW[3];
    int  M[3];
};

#define GB_STRIDE 72

__global__ void __launch_bounds__(256, 2)
k_gemm_ff1(FF1DescB d) {
    extern __shared__ uint32_t dsu[];
    float* dsf = (float*)dsu;
    uint32_t* au = (uint32_t*)d_arena;
    int z = blockIdx.z;
    int M = d.M[z];
    int m0 = blockIdx.y * 128;
    if (m0 >= M) return;
    const int N = 4096, Kw = 256;
    const uint32_t* A  = au + d.offA[z];
    const uint32_t* Bm = au + OFF_WF1 + (long)z * 256 * 4096;
    const float*    bi = d.bip + (long)z * 4096;
    uint32_t*       Gw = au + d.offGW[z];

    int tid  = threadIdx.x;
    int lane = tid & 31, wid = tid >> 5;
    int wm = wid & 3, wn = wid >> 2;
    int g  = lane >> 2, tg = lane & 3;
    int n0 = blockIdx.x * 64;

    int ar  = tid >> 1;
    int ac0 = (tid & 1) << 3;
    int bk  = tid >> 4;
    int bn0 = (tid & 15) << 3;
    int bcol0 = (bn0 < 64) ? (n0 + bn0) : (2048 + n0 + bn0 - 64);

    long grow = m0 + ar;
    long arowc = (grow < M ? grow : (long)(M - 1));
    int  asz = (grow < M) ? 16 : 0;

    float acc[2][8][4];
#pragma unroll
    for (int mi = 0; mi < 2; mi++)
#pragma unroll
        for (int ni = 0; ni < 8; ni++)
#pragma unroll
            for (int r = 0; r < 4; r++) acc[mi][ni][r] = 0.f;

    BF_MAINLOOP(A, Bm, N, Kw, 16)

    // sync before reusing smem for the gelu exchange
    __syncthreads();

    if (wn == 1) {
#pragma unroll
        for (int mi = 0; mi < 2; mi++) {
            int r0 = wm * 32 + mi * 16 + g;
#pragma unroll
            for (int ni = 0; ni < 8; ni++) {
                int c = ni * 8 + tg * 2;
                float bx = bi[2048 + n0 + c], by = bi[2048 + n0 + c + 1];
                float g0 = acc[mi][ni][0] + bx, g1 = acc[mi][ni][1] + by;
                float g2 = acc[mi][ni][2] + bx, g3 = acc[mi][ni][3] + by;
                dsf[r0 * GB_STRIDE + c]           = 0.5f * g0 * (1.f + erff(g0 * 0.7071067811865475f));
                dsf[r0 * GB_STRIDE + c + 1]       = 0.5f * g1 * (1.f + erff(g1 * 0.7071067811865475f));
                dsf[(r0 + 8) * GB_STRIDE + c]     = 0.5f * g2 * (1.f + erff(g2 * 0.7071067811865475f));
                dsf[(r0 + 8) * GB_STRIDE + c + 1] = 0.5f * g3 * (1.f + erff(g3 * 0.7071067811865475f));
            }
        }
    }
    __syncthreads();
    if (wn == 0) {
#pragma unroll
        for (int mi = 0; mi < 2; mi++) {
            int rl = wm * 32 + mi * 16 + g;
            int row = m0 + rl;
#pragma unroll
            for (int ni = 0; ni < 8; ni++) {
                int c = ni * 8 + tg * 2;
                float bx = bi[n0 + c], by = bi[n0 + c + 1];
                if (row < M) {
                    float ox = (acc[mi][ni][0] + bx) * dsf[rl * GB_STRIDE + c];
                    float oy = (acc[mi][ni][1] + by) * dsf[rl * GB_STRIDE + c + 1];
                    Gw[(long)row * 1024 + ((n0 + c) >> 1)] = pack_bf(ox, oy);
                }
                if (row + 8 < M) {
                    float ox = (acc[mi][ni][2] + bx) * dsf[(rl + 8) * GB_STRIDE + c];
                    float oy = (acc[mi][ni][3] + by) * dsf[(rl + 8) * GB_STRIDE + c + 1];
                    Gw[(long)(row + 8) * 1024 + ((n0 + c) >> 1)] = pack_bf(ox, oy);
                }
            }
        }
    }
}

// ---------------------------------------------------------------------------
// FF2 (bf16, K=2048) fused with final residual -> d_out
struct FF2DescB {
    const float* bip;
    float* out;
    long offA[3];
    long tokOff[3];
    int  M[3], len[3], catOff[3];
};

__global__ void __launch_bounds__(256, 2)
k_gemm_ff2(FF2DescB d) {
    extern __shared__ uint32_t dsu[];
    uint32_t* au = (uint32_t*)d_arena;
    int z = blockIdx.z;
    int M = d.M[z];
    int m0 = blockIdx.y * 128;
    if (m0 >= M) return;
    const int N = DM, Kw = 1024;
    const uint32_t* A  = au + d.offA[z];
    const uint32_t* Bm = au + OFF_WF2 + (long)z * 1024 * 512;
    const float*    bi = d.bip + (long)z * DM;

    int tid  = threadIdx.x;
    int lane = tid & 31, wid = tid >> 5;
    int wm = wid & 3, wn = wid >> 2;
    int g  = lane >> 2, tg = lane & 3;
    int n0 = blockIdx.x * 128;

    int ar  = tid >> 1;
    int ac0 = (tid & 1) << 3;
    int bk  = tid >> 4;
    int bn0 = (tid & 15) << 3;
    int bcol0 = n0 + bn0;

    long grow = m0 + ar;
    long arowc = (grow < M ? grow : (long)(M - 1));
    int  asz = (grow < M) ? 16 : 0;

    float acc[2][8][4];
#pragma unroll
    for (int mi = 0; mi < 2; mi++)
#pragma unroll
        for (int ni = 0; ni < 8; ni++)
#pragma unroll
            for (int r = 0; r < 4; r++) acc[mi][ni][r] = 0.f;

    BF_MAINLOOP(A, Bm, N, Kw, 64)

    int len = d.len[z], catOff = d.catOff[z];
    long tokOff = d.tokOff[z];
#pragma unroll
    for (int mi = 0; mi < 2; mi++) {
#pragma unroll
        for (int half = 0; half < 2; half++) {
            int r = m0 + wm * 32 + mi * 16 + g + half * 8;
            if (r >= M) continue;
            int bidx = r / len, t = r - bidx * len;
            float* orow = d.out + ((long)bidx * LL + catOff + t) * DM;
            const float* hrow = d_arena + OFF_HBUF + (tokOff + r) * (long)DM;
            const float* gm = d_arena + OFF_ADA + ((long)z * BB + bidx) * 3072 + 2560;
#pragma unroll
            for (int ni = 0; ni < 8; ni++) {
                int col = n0 + wn * 64 + ni * 8 + tg * 2;
                float fx = acc[mi][ni][half * 2 + 0] + bi[col];
                float fy = acc[mi][ni][half * 2 + 1] + bi[col + 1];
                float2 hv = *(const float2*)&hrow[col];
                float2 gv = *(const float2*)&gm[col];
                float2 o = make_float2(hv.x + gv.x * fx, hv.y + gv.y * fy);
                *(float2*)&orow[col] = o;
            }
        }
    }
}

// ---------------------------------------------------------------------------
__device__ __forceinline__ void block_ln_stats(float s, float q, float* mean, float* ri) {
    __shared__ float sh[8];
    int lane = threadIdx.x & 31, wid = threadIdx.x >> 5;
#pragma unroll
    for (int off = 16; off; off >>= 1) {
        s += __shfl_xor_sync(~0u, s, off);
        q += __shfl_xor_sync(~0u, q, off);
    }
    if (lane == 0) { sh[wid] = s; sh[4 + wid] = q; }
    __syncthreads();
    if (threadIdx.x == 0) {
        float S = sh[0] + sh[1] + sh[2] + sh[3];
        float Q = sh[4] + sh[5] + sh[6] + sh[7];
        float m = S * (1.f / 512.f);
        float v = Q * (1.f / 512.f) - m * m;
        sh[0] = m;
        sh[1] = rsqrtf(v + 1e-6f);
    }
    __syncthreads();
    *mean = sh[0];
    *ri   = sh[1];
}

__device__ __forceinline__ void row_decode(int r, int* istream, int* b, int* t) {
    if (r < 1232)      { *istream = 2; *b = r / TT;            *t = r - *b * TT; }
    else if (r < 6032) { int rr = r - 1232; *istream = 1; *b = rr / SSRC; *t = rr - *b * SSRC; }
    else               { int rr = r - 6032; *istream = 0; *b = rr / NHID; *t = rr - *b * NHID; }
}

__global__ void k_modln(const float* __restrict__ x, const float* __restrict__ src,
                        const float* __restrict__ txt) {
    int row = blockIdx.x;
    int istream, b, t;
    row_decode(row, &istream, &b, &t);
    const float* inp = (istream == 2) ? txt : (istream == 1 ? src : x);
    int lrow = (istream == 2) ? (b * TT + t) : (istream == 1 ? (b * SSRC + t) : (b * NHID + t));
    int tid = threadIdx.x;
    float4 v = *(const float4*)&inp[(long)lrow * DM + tid * 4];
    float s = v.x + v.y + v.z + v.w;
    float q = v.x * v.x + v.y * v.y + v.z * v.z + v.w * v.w;
    float mean, ri;
    block_ln_stats(s, q, &mean, &ri);
    const float* ada = d_arena + OFF_ADA + ((long)istream * BB + b) * 3072;
    float4 sc = *(const float4*)&ada[512 + tid * 4];
    float4 shv = *(const float4*)&ada[tid * 4];
    float ox = (v.x - mean) * ri * (1.f + sc.x) + shv.x;
    float oy = (v.y - mean) * ri * (1.f + sc.y) + shv.y;
    float oz = (v.z - mean) * ri * (1.f + sc.z) + shv.z;
    float ow = (v.w - mean) * ri * (1.f + sc.w) + shv.w;
    uint32_t* au = (uint32_t*)d_arena;
    uint2 pk = make_uint2(pack_bf(ox, oy), pack_bf(oz, ow));
    *(uint2*)&au[OFF_NBUF + (long)row * 256 + tid * 2] = pk;
}

__global__ void k_resln(const float* __restrict__ x, const float* __restrict__ src,
                        const float* __restrict__ txt) {
    int row = blockIdx.x;
    int istream, b, t;
    row_decode(row, &istream, &b, &t);
    const float* inp = (istream == 2) ? txt : (istream == 1 ? src : x);
    int lrow = (istream == 2) ? (b * TT + t) : (istream == 1 ? (b * SSRC + t) : (b * NHID + t));
    int tid = threadIdx.x;
    long rb = (long)row * DM;
    const float* ada = d_arena + OFF_ADA + ((long)istream * BB + b) * 3072;

    float4 x4 = *(const float4*)&inp[(long)lrow * DM + tid * 4];
    float4 a4 = *(const float4*)&d_arena[OFF_ABUF + rb + tid * 4];
    float4 g4 = *(const float4*)&ada[1024 + tid * 4];
    float4 hv;
    hv.x = x4.x + g4.x * a4.x;
    hv.y = x4.y + g4.y * a4.y;
    hv.z = x4.z + g4.z * a4.z;
    hv.w = x4.w + g4.w * a4.w;
    *(float4*)&d_arena[OFF_HBUF + rb + tid * 4] = hv;

    float s = hv.x + hv.y + hv.z + hv.w;
    float q = hv.x * hv.x + hv.y * hv.y + hv.z * hv.z + hv.w * hv.w;
    float mean, ri;
    block_ln_stats(s, q, &mean, &ri);
    float4 sc = *(const float4*)&ada[2048 + tid * 4];
    float4 shv = *(const float4*)&ada[1536 + tid * 4];
    float ox = (hv.x - mean) * ri * (1.f + sc.x) + shv.x;
    float oy = (hv.y - mean) * ri * (1.f + sc.y) + shv.y;
    float oz = (hv.z - mean) * ri * (1.f + sc.z) + shv.z;
    float ow = (hv.w - mean) * ri * (1.f + sc.w) + shv.w;
    uint32_t* au = (uint32_t*)d_arena;
    uint2 pk = make_uint2(pack_bf(ox, oy), pack_bf(oz, ow));
    *(uint2*)&au[OFF_N2 + (long)row * 256 + tid * 2] = pk;
}

// ---------------------------------------------------------------------------
// qkv postprocess (word-based): Q/K only (V stays in QKVW for attention).
// exp2f-based RoPE constants (cheaper than powf; identical to bf16 precision).
__global__ void k_qkvx(const float* __restrict__ gqk,
                       const float* __restrict__ pos_q,
                       const float* __restrict__ pos_k) {
    int w = threadIdx.x >> 5;
    int lane = threadIdx.x & 31;
    int gi = blockIdx.x * 4 + w;
    int h = gi & 7;
    int bl = gi >> 3;
    int l = bl % LL;
    int b = bl / LL;

    int istream, t;
    long r;
    if (l < TT)            { istream = 2; t = l;            r = (long)b * TT + t; }
    else if (l < TT + SSRC){ istream = 1; t = l - TT;       r = 1232 + (long)b * SSRC + t; }
    else                   { istream = 0; t = l - TT - SSRC; r = 6032 + (long)b * NHID + t; }

    uint32_t* au = (uint32_t*)d_arena;
    long base = r * 256 + h * 32 + lane;
    float2 q = unpack_bf(au[OFF_QKVW + base]);
    float2 k = unpack_bf(au[OFF_QKVW + (long)TOKS * 256 + base]);

    float sq = q.x * q.x + q.y * q.y;
    float sk = k.x * k.x + k.y * k.y;
#pragma unroll
    for (int off = 16; off; off >>= 1) {
        sq += __shfl_xor_sync(~0u, sq, off);
        sk += __shfl_xor_sync(~0u, sk, off);
    }
    float rq = rsqrtf(sq * (1.f / 64.f) + 1e-6f);
    float rk = rsqrtf(sk * (1.f / 64.f) + 1e-6f);
    float2 gq = *(const float2*)&gqk[(istream * 2 + 0) * 64 + 2 * lane];
    float2 gk = *(const float2*)&gqk[(istream * 2 + 1) * 64 + 2 * lane];
    q.x *= rq * gq.x; q.y *= rq * gq.y;
    k.x *= rk * gk.x; k.y *= rk * gk.y;

    if (istream == 2) {
        float2 pq = *(const float2*)&pos_q[t * 64 + 2 * lane];
        float2 pk2 = *(const float2*)&pos_k[t * 64 + 2 * lane];
        q.x += pq.x; q.y += pq.y;
        k.x += pk2.x; k.y += pk2.y;
    } else {
        float tf = (float)t;
        float pw = (tf - 150.f) * (1.f / 512.f);
        float dd = (float)(2 * lane);
        // 10000^(-dd/64) = 2^(-dd * log2(10000)/64)
        float inv = exp2f(dd * (-13.287712379549449f / 64.f));
        float ang = tf * inv;
        float c, s;
        sincosf(ang, &s, &c);
        // ((dd + 25.6)/89.6)^pw = 2^(pw * log2((dd+25.6)/89.6))
        float scl = exp2f(pw * __log2f((dd + 25.6f) * (1.f / 89.6f)));
        float csq = c * scl, snq = s * scl;
        float csk = c / scl, snk = s / scl;
        float qe = q.x, qo = q.y, ke = k.x, ko = k.y;
        q.x = qe * csq - qo * snq;
        q.y = qo * csq + qe * snq;
        k.x = ke * csk - ko * snk;
        k.y = ko * csk + ke * snk;
    }

    long wo = ((long)(b * NH + h) * LL + l) * 32 + lane;
    au[OFF_QAW + wo] = pack_bf(q.x, q.y);
    au[OFF_KAW + wo] = pack_bf(k.x, k.y);
}

// ---------------------------------------------------------------------------
// bf16 flash attention (R12-proven: 64 queries/block, 4 warps);
// V staged directly from token-major QKVW via tok_row.
#define QTILES 11
__device__ __forceinline__ int tok_row(int l, int b) {
    if (l < TT)        return b * TT + l;
    if (l < TT + SSRC) return 1232 + b * SSRC + (l - TT);
    return 6032 + b * NHID + (l - TT - SSRC);
}

__global__ void __launch_bounds__(128)
k_attn_tc(const int* __restrict__ valid) {
    __shared__ uint32_t Qs[64][36];
    __shared__ uint32_t Ks[32][36];
    __shared__ uint32_t Vt[64][20];
    __shared__ uint32_t Ps[64][20];
    __shared__ int      sVal[LL];

    uint32_t* au = (uint32_t*)d_arena;
    int tid = threadIdx.x;
    int lane = tid & 31, wid = tid >> 5;
    int g = lane >> 2, tg = lane & 3;
    int bh = blockIdx.x / QTILES;
    int qt = blockIdx.x % QTILES;
    int b = bh >> 3, h = bh & 7;
    int qbase = qt * 64;
    long qkbase = (long)bh * LL * 32;
    const uint32_t* Vg = au + OFF_QKVW + 2L * TOKS * 256;

    for (int m = tid; m < LL; m += 128) sVal[m] = valid[b * LL + m];

    for (int e = tid; e < 512; e += 128) {
        int r = e >> 3, c4 = (e & 7) << 2;
        int l = qbase + r;
        uint4 v = make_uint4(0u, 0u, 0u, 0u);
        if (l < LL) v = *(const uint4*)&au[OFF_QAW + qkbase + (long)l * 32 + c4];
        *(uint4*)&Qs[r][c4] = v;
    }
    __syncthreads();

    int l0 = qbase + wid * 16 + g;
    int l1 = l0 + 8;
    int qv0 = (l0 < LL) ? sVal[l0] : 0;
    int qv1 = (l1 < LL) ? sVal[l1] : 0;

    float m0r = -1e30f, m1r = -1e30f;
    float l0r = 0.f, l1r = 0.f;
    float of[8][4];
#pragma unroll
    for (int ni = 0; ni < 8; ni++)
#pragma unroll
        for (int c = 0; c < 4; c++) of[ni][c] = 0.f;

    int vj2 = tid & 15, vdg = tid >> 4;

    for (int kb = 0; kb < LL; kb += 32) {
        for (int e = tid; e < 256; e += 128) {
            int r = e >> 3, c4 = (e & 7) << 2;
            int m = kb + r;
            uint4 v = make_uint4(0u, 0u, 0u, 0u);
            if (m < LL) v = *(const uint4*)&au[OFF_KAW + qkbase + (long)m * 32 + c4];
            *(uint4*)&Ks[r][c4] = v;
        }
        {
            int ke = kb + 2 * vj2, ko = ke + 1;
            uint4 we = make_uint4(0u, 0u, 0u, 0u), wo = we;
            if (ke < LL) we = *(const uint4*)&Vg[(long)tok_row(ke, b) * 256 + h * 32 + vdg * 4];
            if (ko < LL) wo = *(const uint4*)&Vg[(long)tok_row(ko, b) * 256 + h * 32 + vdg * 4];
            int d0 = vdg * 8;
            Vt[d0 + 0][vj2] = __byte_perm(we.x, wo.x, 0x5410);
            Vt[d0 + 1][vj2] = __byte_perm(we.x, wo.x, 0x7632);
            Vt[d0 + 2][vj2] = __byte_perm(we.y, wo.y, 0x5410);
            Vt[d0 + 3][vj2] = __byte_perm(we.y, wo.y, 0x7632);
            Vt[d0 + 4][vj2] = __byte_perm(we.z, wo.z, 0x5410);
            Vt[d0 + 5][vj2] = __byte_perm(we.z, wo.z, 0x7632);
            Vt[d0 + 6][vj2] = __byte_perm(we.w, wo.w, 0x5410);
            Vt[d0 + 7][vj2] = __byte_perm(we.w, wo.w, 0x7632);
        }
        __syncthreads();

        float sf[4][4];
#pragma unroll
        for (int ni = 0; ni < 4; ni++)
#pragma unroll
            for (int c = 0; c < 4; c++) sf[ni][c] = 0.f;
        int rq = wid * 16 + g;
#pragma unroll
        for (int s = 0; s < 4; s++) {
            uint32_t af[4];
            af[0] = Qs[rq][s * 8 + tg];
            af[1] = Qs[rq + 8][s * 8 + tg];
            af[2] = Qs[rq][s * 8 + tg + 4];
            af[3] = Qs[rq + 8][s * 8 + tg + 4];
#pragma unroll
            for (int ni = 0; ni < 4; ni++) {
                uint32_t bf[2];
                bf[0] = Ks[ni * 8 + g][s * 8 + tg];
                bf[1] = Ks[ni * 8 + g][s * 8 + tg + 4];
                mma_bf16(sf[ni], af, bf);
            }
        }

        float rmax0 = -1e30f, rmax1 = -1e30f;
        float sv[4][4];
        int okm[4][4];
#pragma unroll
        for (int ni = 0; ni < 4; ni++) {
#pragma unroll
            for (int c = 0; c < 2; c++) {
                int key = kb + ni * 8 + tg * 2 + c;
                int kvv = (key < LL) ? sVal[key] : 0;
                int ok0 = (key < LL) && (((qv0 != 0) && (kvv != 0)) || (key == l0));
                int ok1 = (key < LL) && (((qv1 != 0) && (kvv != 0)) || (key == l1));
                float s0 = sf[ni][c] * 0.125f;
                float s1 = sf[ni][c + 2] * 0.125f;
                sv[ni][c] = s0; sv[ni][c + 2] = s1;
                okm[ni][c] = ok0; okm[ni][c + 2] = ok1;
                if (ok0) rmax0 = fmaxf(rmax0, s0);
                if (ok1) rmax1 = fmaxf(rmax1, s1);
            }
        }
        rmax0 = fmaxf(rmax0, __shfl_xor_sync(~0u, rmax0, 1));
        rmax0 = fmaxf(rmax0, __shfl_xor_sync(~0u, rmax0, 2));
        rmax1 = fmaxf(rmax1, __shfl_xor_sync(~0u, rmax1, 1));
        rmax1 = fmaxf(rmax1, __shfl_xor_sync(~0u, rmax1, 2));
        float nm0 = fmaxf(m0r, rmax0);
        float nm1 = fmaxf(m1r, rmax1);
        float corr0 = __expf(m0r - nm0);
        float corr1 = __expf(m1r - nm1);

        float rs0 = 0.f, rs1 = 0.f;
        float pv[4][4];
#pragma unroll
        for (int ni = 0; ni < 4; ni++) {
#pragma unroll
            for (int c = 0; c < 2; c++) {
                float p0 = okm[ni][c]     ? __expf(sv[ni][c] - nm0)     : 0.f;
                float p1 = okm[ni][c + 2] ? __expf(sv[ni][c + 2] - nm1) : 0.f;
                pv[ni][c] = p0; pv[ni][c + 2] = p1;
                rs0 += p0; rs1 += p1;
            }
        }
        rs0 += __shfl_xor_sync(~0u, rs0, 1);
        rs0 += __shfl_xor_sync(~0u, rs0, 2);
        rs1 += __shfl_xor_sync(~0u, rs1, 1);
        rs1 += __shfl_xor_sync(~0u, rs1, 2);
        l0r = l0r * corr0 + rs0;
        l1r = l1r * corr1 + rs1;
        m0r = nm0; m1r = nm1;

#pragma unroll
        for (int ni = 0; ni < 8; ni++) {
            of[ni][0] *= corr0; of[ni][1] *= corr0;
            of[ni][2] *= corr1; of[ni][3] *= corr1;
        }

#pragma unroll
        for (int ni = 0; ni < 4; ni++) {
            Ps[rq][ni * 4 + tg]     = pack_bf(pv[ni][0], pv[ni][1]);
            Ps[rq + 8][ni * 4 + tg] = pack_bf(pv[ni][2], pv[ni][3]);
        }
        __syncwarp();

#pragma unroll
        for (int s = 0; s < 2; s++) {
            uint32_t af[4];
            af[0] = Ps[rq][s * 8 + tg];
            af[1] = Ps[rq + 8][s * 8 + tg];
            af[2] = Ps[rq][s * 8 + tg + 4];
            af[3] = Ps[rq + 8][s * 8 + tg + 4];
#pragma unroll
            for (int ni = 0; ni < 8; ni++) {
                uint32_t bf[2];
                bf[0] = Vt[ni * 8 + g][s * 8 + tg];
                bf[1] = Vt[ni * 8 + g][s * 8 + tg + 4];
                mma_bf16(of[ni], af, bf);
            }
        }
        __syncwarp();
        __syncthreads();
    }

    float inv0 = 1.f / l0r;
    float inv1 = 1.f / l1r;
    if (l0 < LL) {
        long op = (long)tok_row(l0, b) * 256 + h * 32;
#pragma unroll
        for (int ni = 0; ni < 8; ni++)
            au[OFF_OGAT + op + ni * 4 + tg] = pack_bf(of[ni][0] * inv0, of[ni][1] * inv0);
    }
    if (l1 < LL) {
        long op = (long)tok_row(l1, b) * 256 + h * 32;
#pragma unroll
        for (int ni = 0; ni < 8; ni++)
            au[OFF_OGAT + op + ni * 4 + tg] = pack_bf(of[ni][2] * inv1, of[ni][3] * inv1);
    }
}

// ---------------------------------------------------------------------------
extern "C" void kernel_launch(void* const* d_in, const int* in_sizes, int n_in,
                              void* d_out, int out_size) {
    const float* x     = (const float*)d_in[0];
    const float* src   = (const float*)d_in[1];
    const float* txt   = (const float*)d_in[2];
    const float* temb  = (const float*)d_in[3];
    const float* Wqkv  = (const float*)d_in[4];
    const float* bqkv  = (const float*)d_in[5];
    const float* Wo    = (const float*)d_in[6];
    const float* bo    = (const float*)d_in[7];
    const float* gqk   = (const float*)d_in[8];
    const float* Wada  = (const float*)d_in[9];
    const float* bada  = (const float*)d_in[10];
    const float* Wff1  = (const float*)d_in[11];
    const float* bff1  = (const float*)d_in[12];
    const float* Wff2  = (const float*)d_in[13];
    const float* bff2  = (const float*)d_in[14];
    const float* pos_q = (const float*)d_in[15];
    const float* pos_k = (const float*)d_in[16];
    const int*   valid = (const int*)d_in[17];
    float* out = (float*)d_out;

    cudaFuncSetAttribute(k_gemm_bf,  cudaFuncAttributeMaxDynamicSharedMemorySize, GT_SMEM);
    cudaFuncSetAttribute(k_gemm_bfw, cudaFuncAttributeMaxDynamicSharedMemorySize, GT_SMEM);
    cudaFuncSetAttribute(k_gemm_ff1, cudaFuncAttributeMaxDynamicSharedMemorySize, GT_SMEM);
    cudaFuncSetAttribute(k_gemm_ff2, cudaFuncAttributeMaxDynamicSharedMemorySize, GT_SMEM);

    const int  lens[3]    = {NHID, SSRC, TT};
    const long tokOffs[3] = {6032, 1232, 0};
    const int  catOffs[3] = {377, 77, 0};

    // 0. merged weight prepack
    k_wconvAll<<<6144, 256>>>(Wqkv, Wo, Wff1, Wff2);

    // 1. ada = silu(temb) @ Wada[s] + bada[s]
    {
        dim3 g(3072 / 64, 1, 3);
        k_gemm_ada<<<g, 256>>>(temb, Wada, bada, OFF_ADA, BB, 3072, DM,
                               512L * 3072, 3072L, 16L * 3072);
    }

    // 2. modulated LN (merged) -> NBUF bf16
    k_modln<<<TOKS, 128>>>(x, src, txt);

    // 3. QKV GEMMs (bf16 -> packed bf16 words)
    {
        QKVWDesc d;
        d.bip = bqkv;
        for (int s = 0; s < 3; s++) {
            d.offA[s] = OFF_NBUF + tokOffs[s] * 256;
            d.M[s]    = BB * lens[s];
        }
        dim3 g(DM / 128, 38, 9);
        k_gemm_bfw<<<g, 256, GT_SMEM>>>(d);
    }

    // 4. RMS + RoPE/pos -> QAW/KAW
    k_qkvx<<<(BB * LL * NH) / 4, 128>>>(gqk, pos_q, pos_k);

    // 5. attention (bf16 flash) -> OGAT bf16
    k_attn_tc<<<BB * NH * QTILES, 128>>>(valid);

    // 6. output projection (bf16 -> fp32 ABUF)
    {
        GemmDescB d;
        d.bip = bo; d.szBias = DM;
        d.bW = OFF_WO; d.szBW = 256L * 512;
        d.N = DM; d.K = DM;
        for (int z = 0; z < 3; z++) {
            d.offA[z] = OFF_OGAT + tokOffs[z] * 256;
            d.offC[z] = OFF_ABUF + tokOffs[z] * DM;
            d.M[z]    = BB * lens[z];
        }
        dim3 g(DM / 128, 38, 3);
        k_gemm_bf<<<g, 256, GT_SMEM>>>(d);
    }

    // 7. residual + LN2 (merged) -> HBUF fp32, N2 bf16
    k_resln<<<TOKS, 128>>>(x, src, txt);

    // 8. FF1 (bf16) fused GeGLU -> G bf16
    {
        FF1DescB d;
        d.bip = bff1;
        for (int z = 0; z < 3; z++) {
            d.offA[z]  = OFF_N2 + tokOffs[z] * 256;
            d.offGW[z] = OFF_G + tokOffs[z] * 1024;
            d.M[z]     = BB * lens[z];
        }
        dim3 g(2048 / 64, 38, 3);
        k_gemm_ff1<<<g, 256, GT_SMEM>>>(d);
    }

    // 9. FF2 (bf16) fused final residual -> out
    {
        FF2DescB d;
        d.bip = bff2; d.out = out;
        for (int z = 0; z < 3; z++) {
            d.offA[z]   = OFF_G + tokOffs[z] * 1024;
            d.tokOff[z] = tokOffs[z];
            d.M[z]      = BB * lens[z];
            d.len[z]    = lens[z];
            d.catOff[z] = catOffs[z];
        }
        dim3 g(DM / 128, 38, 3);
        k_gemm_ff2<<<g, 256, GT_SMEM>>>(d);
    }
}

// round 17
// speedup vs baseline: 1.0072x; 1.0072x over previous
#include <cuda_runtime.h>
#include <cuda_bf16.h>
#include <math.h>
#include <stdint.h>

#define BB 16
#define TT 77
#define SSRC 300
#define NHID 300
#define LL 677
#define DM 512
#define NH 8
#define HD 64
#define TOKS 10832   // 16*77 + 16*300 + 16*300

// ----- arena offsets (u32/float word units) -----
#define OFF_ADA   8192L          // fp32 3*16*3072
#define OFF_NBUF  155648L        // bf16 words TOKS*256
#define OFF_QKVW  2928640L       // bf16 words 3*TOKS*256 (q,k,v token-major)
#define OFF_QAW   11247616L      // bf16 words [B*H][L][32]
#define OFF_KAW   14020608L
#define OFF_OGAT  19566592L      // bf16 words TOKS*256
#define OFF_ABUF  22339584L      // fp32 TOKS*512
#define OFF_HBUF  27885568L      // fp32 TOKS*512
#define OFF_N2    33431552L      // bf16 words TOKS*256
#define OFF_G     36204544L      // bf16 words TOKS*1024
#define OFF_WQ    47296512L      // 9 * 256*512
#define OFF_WO    48476160L      // 3 * 256*512
#define OFF_WF1   48869376L      // 3 * 256*4096
#define OFF_WF2   52015104L      // 3 * 1024*512
#define ARENA_SZ  53587968L

__device__ float d_arena[ARENA_SZ];

__device__ __forceinline__ uint32_t pack_bf(float x, float y) {
    __nv_bfloat162 h = __floats2bfloat162_rn(x, y);
    return *(uint32_t*)&h;
}
__device__ __forceinline__ float2 unpack_bf(uint32_t w) {
    __nv_bfloat162 h = *(__nv_bfloat162*)&w;
    return __bfloat1622float2(h);
}

// ---------------------------------------------------------------------------
// merged weight prepack: 4 segments in one launch (k-pair packed, row-major)
__global__ void k_wconvAll(const float* __restrict__ W0, const float* __restrict__ W1,
                           const float* __restrict__ W2, const float* __restrict__ W3) {
    int i = blockIdx.x * blockDim.x + threadIdx.x;
    const float* src;
    long dstW;
    int K2, N, base4;
    if (i < 294912)       { src = W0; dstW = OFF_WQ;  K2 = 256;  N = 512;  base4 = 0; }
    else if (i < 393216)  { src = W1; dstW = OFF_WO;  K2 = 256;  N = 512;  base4 = 294912; }
    else if (i < 1179648) { src = W2; dstW = OFF_WF1; K2 = 256;  N = 4096; base4 = 393216; }
    else if (i < 1572864) { src = W3; dstW = OFF_WF2; K2 = 1024; N = 512;  base4 = 1179648; }
    else return;
    int w = (i - base4) << 2;
    int K2N = K2 * N;
    int z = w / K2N;
    int rem = w - z * K2N;
    int k2 = rem / N;
    int n = rem - k2 * N;
    const float* s = src + (long)z * K2N * 2 + (long)(2 * k2) * N + n;
    float4 e = *(const float4*)s;
    float4 o = *(const float4*)(s + N);
    uint4 r;
    r.x = pack_bf(e.x, o.x);
    r.y = pack_bf(e.y, o.y);
    r.z = pack_bf(e.z, o.z);
    r.w = pack_bf(e.w, o.w);
    *(uint4*)&((uint32_t*)d_arena)[dstW + w] = r;
}

// ---------------------------------------------------------------------------
// ada projection SIMT GEMM, silu fused into A staging (M=16)
__global__ void k_gemm_ada(const float* __restrict__ temb,
                           const float* __restrict__ Bmat, const float* __restrict__ bias,
                           long offC, int M, int N, int K,
                           long szB, long szBias, long szC) {
    const float* Bm = Bmat + (long)blockIdx.z * szB;
    const float* bi = bias + (long)blockIdx.z * szBias;
    float*       C  = d_arena + offC + (long)blockIdx.z * szC;

    __shared__ float As[16][68];
    __shared__ float Bs[16][64];

    int tid = threadIdx.x;
    int tx = tid & 15, ty = tid >> 4;
    int arow = tid >> 2;
    int akc  = (tid & 3) << 2;
    int brow = tid >> 4;
    int bcol = (tid & 15) << 2;
    long grow  = (long)blockIdx.y * 64 + arow;
    int  gcolB = blockIdx.x * 64 + bcol;

    float acc[4][4];
#pragma unroll
    for (int i = 0; i < 4; i++)
#pragma unroll
        for (int j = 0; j < 4; j++) acc[i][j] = 0.f;

    for (int kt = 0; kt < K; kt += 16) {
        float4 a4 = make_float4(0.f, 0.f, 0.f, 0.f);
        if (grow < M) {
            a4 = *(const float4*)&temb[grow * K + kt + akc];
            a4.x = a4.x / (1.f + __expf(-a4.x));
            a4.y = a4.y / (1.f + __expf(-a4.y));
            a4.z = a4.z / (1.f + __expf(-a4.z));
            a4.w = a4.w / (1.f + __expf(-a4.w));
        }
        As[akc + 0][arow] = a4.x;
        As[akc + 1][arow] = a4.y;
        As[akc + 2][arow] = a4.z;
        As[akc + 3][arow] = a4.w;
        float4 b4 = *(const float4*)&Bm[(long)(kt + brow) * N + gcolB];
        *(float4*)&Bs[brow][bcol] = b4;
        __syncthreads();
#pragma unroll
        for (int k = 0; k < 16; k++) {
            float4 av = *(const float4*)&As[k][ty << 2];
            float4 bv = *(const float4*)&Bs[k][tx << 2];
            float a[4] = {av.x, av.y, av.z, av.w};
            float b[4] = {bv.x, bv.y, bv.z, bv.w};
#pragma unroll
            for (int i = 0; i < 4; i++)
#pragma unroll
                for (int j = 0; j < 4; j++) acc[i][j] += a[i] * b[j];
        }
        __syncthreads();
    }

    int crow0 = blockIdx.y * 64 + (ty << 2);
    int ccol0 = blockIdx.x * 64 + (tx << 2);
    float4 bi4 = *(const float4*)&bi[ccol0];
#pragma unroll
    for (int i = 0; i < 4; i++) {
        if (crow0 + i < M) {
            float4 o;
            o.x = acc[i][0] + bi4.x;
            o.y = acc[i][1] + bi4.y;
            o.z = acc[i][2] + bi4.z;
            o.w = acc[i][3] + bi4.w;
            *(float4*)&C[(long)(crow0 + i) * N + ccol0] = o;
        }
    }
}

// ---------------------------------------------------------------------------
__device__ __forceinline__ void mma_bf16(float c[4], const uint32_t a[4], const uint32_t b[2]) {
    asm volatile(
        "mma.sync.aligned.m16n8k16.row.col.f32.bf16.bf16.f32 "
        "{%0,%1,%2,%3},{%4,%5,%6,%7},{%8,%9},{%0,%1,%2,%3};"
        : "+f"(c[0]), "+f"(c[1]), "+f"(c[2]), "+f"(c[3])
        : "r"(a[0]), "r"(a[1]), "r"(a[2]), "r"(a[3]), "r"(b[0]), "r"(b[1]));
}

__device__ __forceinline__ uint32_t smem_u32(const void* p) {
    return (uint32_t)__cvta_generic_to_shared(p);
}
__device__ __forceinline__ void cp16(uint32_t dst, const void* src, int sz) {
    asm volatile("cp.async.cg.shared.global [%0], [%1], 16, %2;\n"
                 :: "r"(dst), "l"(src), "r"(sz));
}
__device__ __forceinline__ void cp_commit() { asm volatile("cp.async.commit_group;\n"); }
template <int N> __device__ __forceinline__ void cp_wait() {
    asm volatile("cp.async.wait_group %0;\n" :: "n"(N));
}

// 4-stage bf16 GEMM smem (u32 words): As[4][128][20]=10240, Bs[4][16][136]=8704
#define GT_SMEM 75776
#define AS_IDX(buf, r, k2) ((buf) * 2560 + (r) * 20 + (k2))
#define BS_IDX(buf, k2, n) (10240 + (buf) * 2176 + (k2) * 136 + (n))

// 4-stage ring, single __syncthreads per K-tile (R12-proven form).
#define BF_MAINLOOP(A, Bm, N_, Kw_, nk_)                                                   \
    for (int p = 0; p < 3; p++) {                                                          \
        if (p < (nk_)) {                                                                   \
            const uint32_t* as = (A) + arowc * (Kw_) + (p << 4) + ac0;                     \
            const uint32_t* bs = (Bm) + (long)((p << 4) + bk) * (N_) + bcol0;              \
            for (int c = 0; c < 8; c += 4) cp16(smem_u32(&dsu[AS_IDX(p, ar, ac0 + c)]), as + c, asz); \
            for (int c = 0; c < 8; c += 4) cp16(smem_u32(&dsu[BS_IDX(p, bk, bn0 + c)]), bs + c, 16);  \
        }                                                                                  \
        cp_commit();                                                                       \
    }                                                                                      \
    for (int kt = 0; kt < (nk_); kt++) {                                                   \
        cp_wait<2>();                                                                      \
        __syncthreads();                                                                   \
        if (kt + 3 < (nk_)) {                                                              \
            int nb = (kt + 3) & 3;                                                         \
            const uint32_t* as = (A) + arowc * (Kw_) + ((kt + 3) << 4) + ac0;              \
            const uint32_t* bs = (Bm) + (long)(((kt + 3) << 4) + bk) * (N_) + bcol0;       \
            for (int c = 0; c < 8; c += 4) cp16(smem_u32(&dsu[AS_IDX(nb, ar, ac0 + c)]), as + c, asz); \
            for (int c = 0; c < 8; c += 4) cp16(smem_u32(&dsu[BS_IDX(nb, bk, bn0 + c)]), bs + c, 16);  \
        }                                                                                  \
        cp_commit();                                                                       \
        int cur = kt & 3;                                                                  \
        _Pragma("unroll")                                                                  \
        for (int s8 = 0; s8 < 16; s8 += 8) {                                               \
            uint32_t af[2][4];                                                             \
            _Pragma("unroll")                                                              \
            for (int mi = 0; mi < 2; mi++) {                                               \
                int r = wm * 32 + mi * 16 + g;                                             \
                af[mi][0] = dsu[AS_IDX(cur, r, s8 + tg)];                                  \
                af[mi][1] = dsu[AS_IDX(cur, r + 8, s8 + tg)];                              \
                af[mi][2] = dsu[AS_IDX(cur, r, s8 + tg + 4)];                              \
                af[mi][3] = dsu[AS_IDX(cur, r + 8, s8 + tg + 4)];                          \
            }                                                                              \
            uint32_t bfr[8][2];                                                            \
            _Pragma("unroll")                                                              \
            for (int ni = 0; ni < 8; ni++) {                                               \
                int cn = wn * 64 + ni * 8 + g;                                             \
                bfr[ni][0] = dsu[BS_IDX(cur, s8 + tg, cn)];                                \
                bfr[ni][1] = dsu[BS_IDX(cur, s8 + 4 + tg, cn)];                            \
            }                                                                              \
            _Pragma("unroll")                                                              \
            for (int mi = 0; mi < 2; mi++)                                                 \
                _Pragma("unroll")                                                          \
                for (int ni = 0; ni < 8; ni++)                                             \
                    mma_bf16(acc[mi][ni], af[mi], bfr[ni]);                                \
        }                                                                                  \
    }

// ---------------------------------------------------------------------------
// generic bf16 GEMM -> fp32 C + bias (Wo)
struct GemmDescB {
    const float* bip;
    long szBias;
    long offA[3], offC[3];
    long bW, szBW;
    int  M[3];
    int  N, K;
};

__global__ void __launch_bounds__(256, 2)
k_gemm_bf(GemmDescB d) {
    extern __shared__ uint32_t dsu[];
    uint32_t* au = (uint32_t*)d_arena;
    int z = blockIdx.z;
    int M = d.M[z];
    int m0 = blockIdx.y * 128;
    if (m0 >= M) return;
    int N = d.N;
    int Kw = d.K >> 1;
    const uint32_t* A  = au + d.offA[z];
    const uint32_t* Bm = au + d.bW + (long)z * d.szBW;
    const float*    bi = d.bip + (long)z * d.szBias;
    float*          C  = d_arena + d.offC[z];

    int tid  = threadIdx.x;
    int lane = tid & 31, wid = tid >> 5;
    int wm = wid & 3, wn = wid >> 2;
    int g  = lane >> 2, tg = lane & 3;
    int n0 = blockIdx.x * 128;

    int ar  = tid >> 1;
    int ac0 = (tid & 1) << 3;
    int bk  = tid >> 4;
    int bn0 = (tid & 15) << 3;
    int bcol0 = n0 + bn0;

    long grow = m0 + ar;
    long arowc = (grow < M ? grow : (long)(M - 1));
    int  asz = (grow < M) ? 16 : 0;

    float acc[2][8][4];
#pragma unroll
    for (int mi = 0; mi < 2; mi++)
#pragma unroll
        for (int ni = 0; ni < 8; ni++)
#pragma unroll
            for (int r = 0; r < 4; r++) acc[mi][ni][r] = 0.f;

    int nk = d.K >> 5;
    BF_MAINLOOP(A, Bm, N, Kw, nk)

#pragma unroll
    for (int mi = 0; mi < 2; mi++) {
        int row = m0 + wm * 32 + mi * 16 + g;
#pragma unroll
        for (int ni = 0; ni < 8; ni++) {
            int col = n0 + wn * 64 + ni * 8 + tg * 2;
            float bx = bi[col], by = bi[col + 1];
            if (row < M) {
                float2 o = make_float2(acc[mi][ni][0] + bx, acc[mi][ni][1] + by);
                *(float2*)&C[(long)row * N + col] = o;
            }
            if (row + 8 < M) {
                float2 o = make_float2(acc[mi][ni][2] + bx, acc[mi][ni][3] + by);
                *(float2*)&C[(long)(row + 8) * N + col] = o;
            }
        }
    }
}

// ---------------------------------------------------------------------------
// QKV bf16 GEMM -> PACKED bf16 words (token-major [M][256]); z = s*3+j
struct QKVWDesc {
    const float* bip;
    long offA[3];
    int  M[3];
};

__global__ void __launch_bounds__(256, 2)
k_gemm_bfw(QKVWDesc d) {
    extern __shared__ uint32_t dsu[];
    uint32_t* au = (uint32_t*)d_arena;
    int z = blockIdx.z;
    int s_ = z / 3, j = z % 3;
    int M = d.M[s_];
    int m0 = blockIdx.y * 128;
    if (m0 >= M) return;
    const int N = DM, Kw = 256;
    const uint32_t* A  = au + d.offA[s_];
    const uint32_t* Bm = au + OFF_WQ + (long)z * 256 * 512;
    const float*    bi = d.bip + (long)z * DM;
    uint32_t*       Cw = au + OFF_QKVW + (long)j * TOKS * 256 +
                         (d.offA[s_] - OFF_NBUF);

    int tid  = threadIdx.x;
    int lane = tid & 31, wid = tid >> 5;
    int wm = wid & 3, wn = wid >> 2;
    int g  = lane >> 2, tg = lane & 3;
    int n0 = blockIdx.x * 128;

    int ar  = tid >> 1;
    int ac0 = (tid & 1) << 3;
    int bk  = tid >> 4;
    int bn0 = (tid & 15) << 3;
    int bcol0 = n0 + bn0;

    long grow = m0 + ar;
    long arowc = (grow < M ? grow : (long)(M - 1));
    int  asz = (grow < M) ? 16 : 0;

    float acc[2][8][4];
#pragma unroll
    for (int mi = 0; mi < 2; mi++)
#pragma unroll
        for (int ni = 0; ni < 8; ni++)
#pragma unroll
            for (int r = 0; r < 4; r++) acc[mi][ni][r] = 0.f;

    BF_MAINLOOP(A, Bm, N, Kw, 16)

#pragma unroll
    for (int mi = 0; mi < 2; mi++) {
        int row = m0 + wm * 32 + mi * 16 + g;
#pragma unroll
        for (int ni = 0; ni < 8; ni++) {
            int col = n0 + wn * 64 + ni * 8 + tg * 2;
            float bx = bi[col], by = bi[col + 1];
            if (row < M)
                Cw[(long)row * 256 + (col >> 1)] = pack_bf(acc[mi][ni][0] + bx, acc[mi][ni][1] + by);
            if (row + 8 < M)
                Cw[(long)(row + 8) * 256 + (col >> 1)] = pack_bf(acc[mi][ni][2] + bx, acc[mi][ni][3] + by);
        }
    }
}

// ---------------------------------------------------------------------------
// FF1 (bf16) fused with GeGLU -> G (bf16)
struct FF1DescB {
    const float* bip;
    long offA[3], offGW[3];
    int  M[3];
};

#define GB_STRIDE 72

__global__ void __launch_bounds__(256, 2)
k_gemm_ff1(FF1DescB d) {
    extern __shared__ uint32_t dsu[];
    float* dsf = (float*)dsu;
    uint32_t* au = (uint32_t*)d_arena;
    int z = blockIdx.z;
    int M = d.M[z];
    int m0 = blockIdx.y * 128;
    if (m0 >= M) return;
    const int N = 4096, Kw = 256;
    const uint32_t* A  = au + d.offA[z];
    const uint32_t* Bm = au + OFF_WF1 + (long)z * 256 * 4096;
    const float*    bi = d.bip + (long)z * 4096;
    uint32_t*       Gw = au + d.offGW[z];

    int tid  = threadIdx.x;
    int lane = tid & 31, wid = tid >> 5;
    int wm = wid & 3, wn = wid >> 2;
    int g  = lane >> 2, tg = lane & 3;
    int n0 = blockIdx.x * 64;

    int ar  = tid >> 1;
    int ac0 = (tid & 1) << 3;
    int bk  = tid >> 4;
    int bn0 = (tid & 15) << 3;
    int bcol0 = (bn0 < 64) ? (n0 + bn0) : (2048 + n0 + bn0 - 64);

    long grow = m0 + ar;
    long arowc = (grow < M ? grow : (long)(M - 1));
    int  asz = (grow < M) ? 16 : 0;

    float acc[2][8][4];
#pragma unroll
    for (int mi = 0; mi < 2; mi++)
#pragma unroll
        for (int ni = 0; ni < 8; ni++)
#pragma unroll
            for (int r = 0; r < 4; r++) acc[mi][ni][r] = 0.f;

    BF_MAINLOOP(A, Bm, N, Kw, 16)

    // sync before reusing smem for the gelu exchange
    __syncthreads();

    if (wn == 1) {
#pragma unroll
        for (int mi = 0; mi < 2; mi++) {
            int r0 = wm * 32 + mi * 16 + g;
#pragma unroll
            for (int ni = 0; ni < 8; ni++) {
                int c = ni * 8 + tg * 2;
                float bx = bi[2048 + n0 + c], by = bi[2048 + n0 + c + 1];
                float g0 = acc[mi][ni][0] + bx, g1 = acc[mi][ni][1] + by;
                float g2 = acc[mi][ni][2] + bx, g3 = acc[mi][ni][3] + by;
                dsf[r0 * GB_STRIDE + c]           = 0.5f * g0 * (1.f + erff(g0 * 0.7071067811865475f));
                dsf[r0 * GB_STRIDE + c + 1]       = 0.5f * g1 * (1.f + erff(g1 * 0.7071067811865475f));
                dsf[(r0 + 8) * GB_STRIDE + c]     = 0.5f * g2 * (1.f + erff(g2 * 0.7071067811865475f));
                dsf[(r0 + 8) * GB_STRIDE + c + 1] = 0.5f * g3 * (1.f + erff(g3 * 0.7071067811865475f));
            }
        }
    }
    __syncthreads();
    if (wn == 0) {
#pragma unroll
        for (int mi = 0; mi < 2; mi++) {
            int rl = wm * 32 + mi * 16 + g;
            int row = m0 + rl;
#pragma unroll
            for (int ni = 0; ni < 8; ni++) {
                int c = ni * 8 + tg * 2;
                float bx = bi[n0 + c], by = bi[n0 + c + 1];
                if (row < M) {
                    float ox = (acc[mi][ni][0] + bx) * dsf[rl * GB_STRIDE + c];
                    float oy = (acc[mi][ni][1] + by) * dsf[rl * GB_STRIDE + c + 1];
                    Gw[(long)row * 1024 + ((n0 + c) >> 1)] = pack_bf(ox, oy);
                }
                if (row + 8 < M) {
                    float ox = (acc[mi][ni][2] + bx) * dsf[(rl + 8) * GB_STRIDE + c];
                    float oy = (acc[mi][ni][3] + by) * dsf[(rl + 8) * GB_STRIDE + c + 1];
                    Gw[(long)(row + 8) * 1024 + ((n0 + c) >> 1)] = pack_bf(ox, oy);
                }
            }
        }
    }
}

// ---------------------------------------------------------------------------
// FF2 (bf16, K=2048) fused with final residual -> d_out
struct FF2DescB {
    const float* bip;
    float* out;
    long offA[3];
    long tokOff[3];
    int  M[3], len[3], catOff[3];
};

__global__ void __launch_bounds__(256, 2)
k_gemm_ff2(FF2DescB d) {
    extern __shared__ uint32_t dsu[];
    uint32_t* au = (uint32_t*)d_arena;
    int z = blockIdx.z;
    int M = d.M[z];
    int m0 = blockIdx.y * 128;
    if (m0 >= M) return;
    const int N = DM, Kw = 1024;
    const uint32_t* A  = au + d.offA[z];
    const uint32_t* Bm = au + OFF_WF2 + (long)z * 1024 * 512;
    const float*    bi = d.bip + (long)z * DM;

    int tid  = threadIdx.x;
    int lane = tid & 31, wid = tid >> 5;
    int wm = wid & 3, wn = wid >> 2;
    int g  = lane >> 2, tg = lane & 3;
    int n0 = blockIdx.x * 128;

    int ar  = tid >> 1;
    int ac0 = (tid & 1) << 3;
    int bk  = tid >> 4;
    int bn0 = (tid & 15) << 3;
    int bcol0 = n0 + bn0;

    long grow = m0 + ar;
    long arowc = (grow < M ? grow : (long)(M - 1));
    int  asz = (grow < M) ? 16 : 0;

    float acc[2][8][4];
#pragma unroll
    for (int mi = 0; mi < 2; mi++)
#pragma unroll
        for (int ni = 0; ni < 8; ni++)
#pragma unroll
            for (int r = 0; r < 4; r++) acc[mi][ni][r] = 0.f;

    BF_MAINLOOP(A, Bm, N, Kw, 64)

    int len = d.len[z], catOff = d.catOff[z];
    long tokOff = d.tokOff[z];
#pragma unroll
    for (int mi = 0; mi < 2; mi++) {
#pragma unroll
        for (int half = 0; half < 2; half++) {
            int r = m0 + wm * 32 + mi * 16 + g + half * 8;
            if (r >= M) continue;
            int bidx = r / len, t = r - bidx * len;
            float* orow = d.out + ((long)bidx * LL + catOff + t) * DM;
            const float* hrow = d_arena + OFF_HBUF + (tokOff + r) * (long)DM;
            const float* gm = d_arena + OFF_ADA + ((long)z * BB + bidx) * 3072 + 2560;
#pragma unroll
            for (int ni = 0; ni < 8; ni++) {
                int col = n0 + wn * 64 + ni * 8 + tg * 2;
                float fx = acc[mi][ni][half * 2 + 0] + bi[col];
                float fy = acc[mi][ni][half * 2 + 1] + bi[col + 1];
                float2 hv = *(const float2*)&hrow[col];
                float2 gv = *(const float2*)&gm[col];
                float2 o = make_float2(hv.x + gv.x * fx, hv.y + gv.y * fy);
                *(float2*)&orow[col] = o;
            }
        }
    }
}

// ---------------------------------------------------------------------------
__device__ __forceinline__ void block_ln_stats(float s, float q, float* mean, float* ri) {
    __shared__ float sh[8];
    int lane = threadIdx.x & 31, wid = threadIdx.x >> 5;
#pragma unroll
    for (int off = 16; off; off >>= 1) {
        s += __shfl_xor_sync(~0u, s, off);
        q += __shfl_xor_sync(~0u, q, off);
    }
    if (lane == 0) { sh[wid] = s; sh[4 + wid] = q; }
    __syncthreads();
    if (threadIdx.x == 0) {
        float S = sh[0] + sh[1] + sh[2] + sh[3];
        float Q = sh[4] + sh[5] + sh[6] + sh[7];
        float m = S * (1.f / 512.f);
        float v = Q * (1.f / 512.f) - m * m;
        sh[0] = m;
        sh[1] = rsqrtf(v + 1e-6f);
    }
    __syncthreads();
    *mean = sh[0];
    *ri   = sh[1];
}

__device__ __forceinline__ void row_decode(int r, int* istream, int* b, int* t) {
    if (r < 1232)      { *istream = 2; *b = r / TT;            *t = r - *b * TT; }
    else if (r < 6032) { int rr = r - 1232; *istream = 1; *b = rr / SSRC; *t = rr - *b * SSRC; }
    else               { int rr = r - 6032; *istream = 0; *b = rr / NHID; *t = rr - *b * NHID; }
}

__global__ void k_modln(const float* __restrict__ x, const float* __restrict__ src,
                        const float* __restrict__ txt) {
    int row = blockIdx.x;
    int istream, b, t;
    row_decode(row, &istream, &b, &t);
    const float* inp = (istream == 2) ? txt : (istream == 1 ? src : x);
    int lrow = (istream == 2) ? (b * TT + t) : (istream == 1 ? (b * SSRC + t) : (b * NHID + t));
    int tid = threadIdx.x;
    float4 v = *(const float4*)&inp[(long)lrow * DM + tid * 4];
    float s = v.x + v.y + v.z + v.w;
    float q = v.x * v.x + v.y * v.y + v.z * v.z + v.w * v.w;
    float mean, ri;
    block_ln_stats(s, q, &mean, &ri);
    const float* ada = d_arena + OFF_ADA + ((long)istream * BB + b) * 3072;
    float4 sc = *(const float4*)&ada[512 + tid * 4];
    float4 shv = *(const float4*)&ada[tid * 4];
    float ox = (v.x - mean) * ri * (1.f + sc.x) + shv.x;
    float oy = (v.y - mean) * ri * (1.f + sc.y) + shv.y;
    float oz = (v.z - mean) * ri * (1.f + sc.z) + shv.z;
    float ow = (v.w - mean) * ri * (1.f + sc.w) + shv.w;
    uint32_t* au = (uint32_t*)d_arena;
    uint2 pk = make_uint2(pack_bf(ox, oy), pack_bf(oz, ow));
    *(uint2*)&au[OFF_NBUF + (long)row * 256 + tid * 2] = pk;
}

__global__ void k_resln(const float* __restrict__ x, const float* __restrict__ src,
                        const float* __restrict__ txt) {
    int row = blockIdx.x;
    int istream, b, t;
    row_decode(row, &istream, &b, &t);
    const float* inp = (istream == 2) ? txt : (istream == 1 ? src : x);
    int lrow = (istream == 2) ? (b * TT + t) : (istream == 1 ? (b * SSRC + t) : (b * NHID + t));
    int tid = threadIdx.x;
    long rb = (long)row * DM;
    const float* ada = d_arena + OFF_ADA + ((long)istream * BB + b) * 3072;

    float4 x4 = *(const float4*)&inp[(long)lrow * DM + tid * 4];
    float4 a4 = *(const float4*)&d_arena[OFF_ABUF + rb + tid * 4];
    float4 g4 = *(const float4*)&ada[1024 + tid * 4];
    float4 hv;
    hv.x = x4.x + g4.x * a4.x;
    hv.y = x4.y + g4.y * a4.y;
    hv.z = x4.z + g4.z * a4.z;
    hv.w = x4.w + g4.w * a4.w;
    *(float4*)&d_arena[OFF_HBUF + rb + tid * 4] = hv;

    float s = hv.x + hv.y + hv.z + hv.w;
    float q = hv.x * hv.x + hv.y * hv.y + hv.z * hv.z + hv.w * hv.w;
    float mean, ri;
    block_ln_stats(s, q, &mean, &ri);
    float4 sc = *(const float4*)&ada[2048 + tid * 4];
    float4 shv = *(const float4*)&ada[1536 + tid * 4];
    float ox = (hv.x - mean) * ri * (1.f + sc.x) + shv.x;
    float oy = (hv.y - mean) * ri * (1.f + sc.y) + shv.y;
    float oz = (hv.z - mean) * ri * (1.f + sc.z) + shv.z;
    float ow = (hv.w - mean) * ri * (1.f + sc.w) + shv.w;
    uint32_t* au = (uint32_t*)d_arena;
    uint2 pk = make_uint2(pack_bf(ox, oy), pack_bf(oz, ow));
    *(uint2*)&au[OFF_N2 + (long)row * 256 + tid * 2] = pk;
}

// ---------------------------------------------------------------------------
// qkv postprocess (word-based): Q/K only (V stays in QKVW for attention).
// exp2f-based RoPE constants (cheaper than powf; identical to bf16 precision).
__global__ void k_qkvx(const float* __restrict__ gqk,
                       const float* __restrict__ pos_q,
                       const float* __restrict__ pos_k) {
    int w = threadIdx.x >> 5;
    int lane = threadIdx.x & 31;
    int gi = blockIdx.x * 4 + w;
    int h = gi & 7;
    int bl = gi >> 3;
    int l = bl % LL;
    int b = bl / LL;

    int istream, t;
    long r;
    if (l < TT)            { istream = 2; t = l;            r = (long)b * TT + t; }
    else if (l < TT + SSRC){ istream = 1; t = l - TT;       r = 1232 + (long)b * SSRC + t; }
    else                   { istream = 0; t = l - TT - SSRC; r = 6032 + (long)b * NHID + t; }

    uint32_t* au = (uint32_t*)d_arena;
    long base = r * 256 + h * 32 + lane;
    float2 q = unpack_bf(au[OFF_QKVW + base]);
    float2 k = unpack_bf(au[OFF_QKVW + (long)TOKS * 256 + base]);

    float sq = q.x * q.x + q.y * q.y;
    float sk = k.x * k.x + k.y * k.y;
#pragma unroll
    for (int off = 16; off; off >>= 1) {
        sq += __shfl_xor_sync(~0u, sq, off);
        sk += __shfl_xor_sync(~0u, sk, off);
    }
    float rq = rsqrtf(sq * (1.f / 64.f) + 1e-6f);
    float rk = rsqrtf(sk * (1.f / 64.f) + 1e-6f);
    float2 gq = *(const float2*)&gqk[(istream * 2 + 0) * 64 + 2 * lane];
    float2 gk = *(const float2*)&gqk[(istream * 2 + 1) * 64 + 2 * lane];
    q.x *= rq * gq.x; q.y *= rq * gq.y;
    k.x *= rk * gk.x; k.y *= rk * gk.y;

    if (istream == 2) {
        float2 pq = *(const float2*)&pos_q[t * 64 + 2 * lane];
        float2 pk2 = *(const float2*)&pos_k[t * 64 + 2 * lane];
        q.x += pq.x; q.y += pq.y;
        k.x += pk2.x; k.y += pk2.y;
    } else {
        float tf = (float)t;
        float pw = (tf - 150.f) * (1.f / 512.f);
        float dd = (float)(2 * lane);
        // 10000^(-dd/64) = 2^(-dd * log2(10000)/64)
        float inv = exp2f(dd * (-13.287712379549449f / 64.f));
        float ang = tf * inv;
        float c, s;
        sincosf(ang, &s, &c);
        // ((dd + 25.6)/89.6)^pw = 2^(pw * log2((dd+25.6)/89.6))
        float scl = exp2f(pw * __log2f((dd + 25.6f) * (1.f / 89.6f)));
        float csq = c * scl, snq = s * scl;
        float csk = c / scl, snk = s / scl;
        float qe = q.x, qo = q.y, ke = k.x, ko = k.y;
        q.x = qe * csq - qo * snq;
        q.y = qo * csq + qe * snq;
        k.x = ke * csk - ko * snk;
        k.y = ko * csk + ke * snk;
    }

    long wo = ((long)(b * NH + h) * LL + l) * 32 + lane;
    au[OFF_QAW + wo] = pack_bf(q.x, q.y);
    au[OFF_KAW + wo] = pack_bf(k.x, k.y);
}

// ---------------------------------------------------------------------------
// bf16 flash attention (R12-proven: 64 queries/block, 4 warps);
// V staged directly from token-major QKVW via tok_row.
#define QTILES 11
__device__ __forceinline__ int tok_row(int l, int b) {
    if (l < TT)        return b * TT + l;
    if (l < TT + SSRC) return 1232 + b * SSRC + (l - TT);
    return 6032 + b * NHID + (l - TT - SSRC);
}

__global__ void __launch_bounds__(128)
k_attn_tc(const int* __restrict__ valid) {
    __shared__ uint32_t Qs[64][36];
    __shared__ uint32_t Ks[32][36];
    __shared__ uint32_t Vt[64][20];
    __shared__ uint32_t Ps[64][20];
    __shared__ int      sVal[LL];

    uint32_t* au = (uint32_t*)d_arena;
    int tid = threadIdx.x;
    int lane = tid & 31, wid = tid >> 5;
    int g = lane >> 2, tg = lane & 3;
    int bh = blockIdx.x / QTILES;
    int qt = blockIdx.x % QTILES;
    int b = bh >> 3, h = bh & 7;
    int qbase = qt * 64;
    long qkbase = (long)bh * LL * 32;
    const uint32_t* Vg = au + OFF_QKVW + 2L * TOKS * 256;

    for (int m = tid; m < LL; m += 128) sVal[m] = valid[b * LL + m];

    for (int e = tid; e < 512; e += 128) {
        int r = e >> 3, c4 = (e & 7) << 2;
        int l = qbase + r;
        uint4 v = make_uint4(0u, 0u, 0u, 0u);
        if (l < LL) v = *(const uint4*)&au[OFF_QAW + qkbase + (long)l * 32 + c4];
        *(uint4*)&Qs[r][c4] = v;
    }
    __syncthreads();

    int l0 = qbase + wid * 16 + g;
    int l1 = l0 + 8;
    int qv0 = (l0 < LL) ? sVal[l0] : 0;
    int qv1 = (l1 < LL) ? sVal[l1] : 0;

    float m0r = -1e30f, m1r = -1e30f;
    float l0r = 0.f, l1r = 0.f;
    float of[8][4];
#pragma unroll
    for (int ni = 0; ni < 8; ni++)
#pragma unroll
        for (int c = 0; c < 4; c++) of[ni][c] = 0.f;

    int vj2 = tid & 15, vdg = tid >> 4;

    for (int kb = 0; kb < LL; kb += 32) {
        for (int e = tid; e < 256; e += 128) {
            int r = e >> 3, c4 = (e & 7) << 2;
            int m = kb + r;
            uint4 v = make_uint4(0u, 0u, 0u, 0u);
            if (m < LL) v = *(const uint4*)&au[OFF_KAW + qkbase + (long)m * 32 + c4];
            *(uint4*)&Ks[r][c4] = v;
        }
        {
            int ke = kb + 2 * vj2, ko = ke + 1;
            uint4 we = make_uint4(0u, 0u, 0u, 0u), wo = we;
            if (ke < LL) we = *(const uint4*)&Vg[(long)tok_row(ke, b) * 256 + h * 32 + vdg * 4];
            if (ko < LL) wo = *(const uint4*)&Vg[(long)tok_row(ko, b) * 256 + h * 32 + vdg * 4];
            int d0 = vdg * 8;
            Vt[d0 + 0][vj2] = __byte_perm(we.x, wo.x, 0x5410);
            Vt[d0 + 1][vj2] = __byte_perm(we.x, wo.x, 0x7632);
            Vt[d0 + 2][vj2] = __byte_perm(we.y, wo.y, 0x5410);
            Vt[d0 + 3][vj2] = __byte_perm(we.y, wo.y, 0x7632);
            Vt[d0 + 4][vj2] = __byte_perm(we.z, wo.z, 0x5410);
            Vt[d0 + 5][vj2] = __byte_perm(we.z, wo.z, 0x7632);
            Vt[d0 + 6][vj2] = __byte_perm(we.w, wo.w, 0x5410);
            Vt[d0 + 7][vj2] = __byte_perm(we.w, wo.w, 0x7632);
        }
        __syncthreads();

        float sf[4][4];
#pragma unroll
        for (int ni = 0; ni < 4; ni++)
#pragma unroll
            for (int c = 0; c < 4; c++) sf[ni][c] = 0.f;
        int rq = wid * 16 + g;
#pragma unroll
        for (int s = 0; s < 4; s++) {
            uint32_t af[4];
            af[0] = Qs[rq][s * 8 + tg];
            af[1] = Qs[rq + 8][s * 8 + tg];
            af[2] = Qs[rq][s * 8 + tg + 4];
            af[3] = Qs[rq + 8][s * 8 + tg + 4];
#pragma unroll
            for (int ni = 0; ni < 4; ni++) {
                uint32_t bf[2];
                bf[0] = Ks[ni * 8 + g][s * 8 + tg];
                bf[1] = Ks[ni * 8 + g][s * 8 + tg + 4];
                mma_bf16(sf[ni], af, bf);
            }
        }

        float rmax0 = -1e30f, rmax1 = -1e30f;
        float sv[4][4];
        int okm[4][4];
#pragma unroll
        for (int ni = 0; ni < 4; ni++) {
#pragma unroll
            for (int c = 0; c < 2; c++) {
                int key = kb + ni * 8 + tg * 2 + c;
                int kvv = (key < LL) ? sVal[key] : 0;
                int ok0 = (key < LL) && (((qv0 != 0) && (kvv != 0)) || (key == l0));
                int ok1 = (key < LL) && (((qv1 != 0) && (kvv != 0)) || (key == l1));
                float s0 = sf[ni][c] * 0.125f;
                float s1 = sf[ni][c + 2] * 0.125f;
                sv[ni][c] = s0; sv[ni][c + 2] = s1;
                okm[ni][c] = ok0; okm[ni][c + 2] = ok1;
                if (ok0) rmax0 = fmaxf(rmax0, s0);
                if (ok1) rmax1 = fmaxf(rmax1, s1);
            }
        }
        rmax0 = fmaxf(rmax0, __shfl_xor_sync(~0u, rmax0, 1));
        rmax0 = fmaxf(rmax0, __shfl_xor_sync(~0u, rmax0, 2));
        rmax1 = fmaxf(rmax1, __shfl_xor_sync(~0u, rmax1, 1));
        rmax1 = fmaxf(rmax1, __shfl_xor_sync(~0u, rmax1, 2));
        float nm0 = fmaxf(m0r, rmax0);
        float nm1 = fmaxf(m1r, rmax1);
        float corr0 = __expf(m0r - nm0);
        float corr1 = __expf(m1r - nm1);

        float rs0 = 0.f, rs1 = 0.f;
        float pv[4][4];
#pragma unroll
        for (int ni = 0; ni < 4; ni++) {
#pragma unroll
            for (int c = 0; c < 2; c++) {
                float p0 = okm[ni][c]     ? __expf(sv[ni][c] - nm0)     : 0.f;
                float p1 = okm[ni][c + 2] ? __expf(sv[ni][c + 2] - nm1) : 0.f;
                pv[ni][c] = p0; pv[ni][c + 2] = p1;
                rs0 += p0; rs1 += p1;
            }
        }
        rs0 += __shfl_xor_sync(~0u, rs0, 1);
        rs0 += __shfl_xor_sync(~0u, rs0, 2);
        rs1 += __shfl_xor_sync(~0u, rs1, 1);
        rs1 += __shfl_xor_sync(~0u, rs1, 2);
        l0r = l0r * corr0 + rs0;
        l1r = l1r * corr1 + rs1;
        m0r = nm0; m1r = nm1;

#pragma unroll
        for (int ni = 0; ni < 8; ni++) {
            of[ni][0] *= corr0; of[ni][1] *= corr0;
            of[ni][2] *= corr1; of[ni][3] *= corr1;
        }

#pragma unroll
        for (int ni = 0; ni < 4; ni++) {
            Ps[rq][ni * 4 + tg]     = pack_bf(pv[ni][0], pv[ni][1]);
            Ps[rq + 8][ni * 4 + tg] = pack_bf(pv[ni][2], pv[ni][3]);
        }
        __syncwarp();

#pragma unroll
        for (int s = 0; s < 2; s++) {
            uint32_t af[4];
            af[0] = Ps[rq][s * 8 + tg];
            af[1] = Ps[rq + 8][s * 8 + tg];
            af[2] = Ps[rq][s * 8 + tg + 4];
            af[3] = Ps[rq + 8][s * 8 + tg + 4];
#pragma unroll
            for (int ni = 0; ni < 8; ni++) {
                uint32_t bf[2];
                bf[0] = Vt[ni * 8 + g][s * 8 + tg];
                bf[1] = Vt[ni * 8 + g][s * 8 + tg + 4];
                mma_bf16(of[ni], af, bf);
            }
        }
        __syncwarp();
        __syncthreads();
    }

    float inv0 = 1.f / l0r;
    float inv1 = 1.f / l1r;
    if (l0 < LL) {
        long op = (long)tok_row(l0, b) * 256 + h * 32;
#pragma unroll
        for (int ni = 0; ni < 8; ni++)
            au[OFF_OGAT + op + ni * 4 + tg] = pack_bf(of[ni][0] * inv0, of[ni][1] * inv0);
    }
    if (l1 < LL) {
        long op = (long)tok_row(l1, b) * 256 + h * 32;
#pragma unroll
        for (int ni = 0; ni < 8; ni++)
            au[OFF_OGAT + op + ni * 4 + tg] = pack_bf(of[ni][2] * inv1, of[ni][3] * inv1);
    }
}

// ---------------------------------------------------------------------------
extern "C" void kernel_launch(void* const* d_in, const int* in_sizes, int n_in,
                              void* d_out, int out_size) {
    const float* x     = (const float*)d_in[0];
    const float* src   = (const float*)d_in[1];
    const float* txt   = (const float*)d_in[2];
    const float* temb  = (const float*)d_in[3];
    const float* Wqkv  = (const float*)d_in[4];
    const float* bqkv  = (const float*)d_in[5];
    const float* Wo    = (const float*)d_in[6];
    const float* bo    = (const float*)d_in[7];
    const float* gqk   = (const float*)d_in[8];
    const float* Wada  = (const float*)d_in[9];
    const float* bada  = (const float*)d_in[10];
    const float* Wff1  = (const float*)d_in[11];
    const float* bff1  = (const float*)d_in[12];
    const float* Wff2  = (const float*)d_in[13];
    const float* bff2  = (const float*)d_in[14];
    const float* pos_q = (const float*)d_in[15];
    const float* pos_k = (const float*)d_in[16];
    const int*   valid = (const int*)d_in[17];
    float* out = (float*)d_out;

    cudaFuncSetAttribute(k_gemm_bf,  cudaFuncAttributeMaxDynamicSharedMemorySize, GT_SMEM);
    cudaFuncSetAttribute(k_gemm_bfw, cudaFuncAttributeMaxDynamicSharedMemorySize, GT_SMEM);
    cudaFuncSetAttribute(k_gemm_ff1, cudaFuncAttributeMaxDynamicSharedMemorySize, GT_SMEM);
    cudaFuncSetAttribute(k_gemm_ff2, cudaFuncAttributeMaxDynamicSharedMemorySize, GT_SMEM);

    const int  lens[3]    = {NHID, SSRC, TT};
    const long tokOffs[3] = {6032, 1232, 0};
    const int  catOffs[3] = {377, 77, 0};

    // 0. merged weight prepack
    k_wconvAll<<<6144, 256>>>(Wqkv, Wo, Wff1, Wff2);

    // 1. ada = silu(temb) @ Wada[s] + bada[s]
    {
        dim3 g(3072 / 64, 1, 3);
        k_gemm_ada<<<g, 256>>>(temb, Wada, bada, OFF_ADA, BB, 3072, DM,
                               512L * 3072, 3072L, 16L * 3072);
    }

    // 2. modulated LN (merged) -> NBUF bf16
    k_modln<<<TOKS, 128>>>(x, src, txt);

    // 3. QKV GEMMs (bf16 -> packed bf16 words)
    {
        QKVWDesc d;
        d.bip = bqkv;
        for (int s = 0; s < 3; s++) {
            d.offA[s] = OFF_NBUF + tokOffs[s] * 256;
            d.M[s]    = BB * lens[s];
        }
        dim3 g(DM / 128, 38, 9);
        k_gemm_bfw<<<g, 256, GT_SMEM>>>(d);
    }

    // 4. RMS + RoPE/pos -> QAW/KAW
    k_qkvx<<<(BB * LL * NH) / 4, 128>>>(gqk, pos_q, pos_k);

    // 5. attention (bf16 flash) -> OGAT bf16
    k_attn_tc<<<BB * NH * QTILES, 128>>>(valid);

    // 6. output projection (bf16 -> fp32 ABUF)
    {
        GemmDescB d;
        d.bip = bo; d.szBias = DM;
        d.bW = OFF_WO; d.szBW = 256L * 512;
        d.N = DM; d.K = DM;
        for (int z = 0; z < 3; z++) {
            d.offA[z] = OFF_OGAT + tokOffs[z] * 256;
            d.offC[z] = OFF_ABUF + tokOffs[z] * DM;
            d.M[z]    = BB * lens[z];
        }
        dim3 g(DM / 128, 38, 3);
        k_gemm_bf<<<g, 256, GT_SMEM>>>(d);
    }

    // 7. residual + LN2 (merged) -> HBUF fp32, N2 bf16
    k_resln<<<TOKS, 128>>>(x, src, txt);

    // 8. FF1 (bf16) fused GeGLU -> G bf16
    {
        FF1DescB d;
        d.bip = bff1;
        for (int z = 0; z < 3; z++) {
            d.offA[z]  = OFF_N2 + tokOffs[z] * 256;
            d.offGW[z] = OFF_G + tokOffs[z] * 1024;
            d.M[z]     = BB * lens[z];
        }
        dim3 g(2048 / 64, 38, 3);
        k_gemm_ff1<<<g, 256, GT_SMEM>>>(d);
    }

    // 9. FF2 (bf16) fused final residual -> out
    {
        FF2DescB d;
        d.bip = bff2; d.out = out;
        for (int z = 0; z < 3; z++) {
            d.offA[z]   = OFF_G + tokOffs[z] * 1024;
            d.tokOff[z] = tokOffs[z];
            d.M[z]      = BB * lens[z];
            d.len[z]    = lens[z];
            d.catOff[z] = catOffs[z];
        }
        dim3 g(DM / 128, 38, 3);
        k_gemm_ff2<<<g, 256, GT_SMEM>>>(d);
    }
}